// round 12
// baseline (speedup 1.0000x reference)
#include <cuda_runtime.h>
#include <cstdint>

// LIF neuron scan — hybrid: non-tensor cp.async.bulk input pipeline (no
// tensormap, plain pointers -> no per-replay descriptor overhead) + float4
// wide stores (512 B warp bursts, 1 KB contiguous per CTA per timestep).
// 128 CTAs x 64 threads (2 warps); CTA tile = 256 neurons; thread = 4.
//
// Inputs : d_in[0] = input_current  f32 [B=32, T=1000, N=1024]
//          d_in[1] = v_init         f32 [B=32, N=1024]
// Output : d_out = [2, B, T, N] f32  (spikes block, then voltages block)
//
// Recurrence:
//   v = v + (i - v) / 10.0     (correctly-rounded div via Markstein FMA seq)
//   s = (v >= 1.0) ? 1 : 0
//   v = s ? 0 : v

#define LIF_B   32
#define LIF_T   1000
#define LIF_N   1024
#define TC      20                    // timesteps per chunk
#define NSTAGE  6                     // input pipeline depth
#define NPC     256                   // neurons per CTA
#define NTHREAD 64                    // threads per CTA (4 neurons each)
#define NCHUNK  (LIF_T / TC)          // 50
#define ROW_BYTES (NPC * 4)           // 1024
#define STAGE_BYTES (TC * ROW_BYTES)  // 20480
#define NCTA    (LIF_B * (LIF_N / NPC))  // 128

struct LifSmem {
    float tile[NSTAGE][TC][NPC];      // 6*20*256*4 = 122880 B
    unsigned long long mbar[NSTAGE];
};

static __device__ __forceinline__ unsigned smem_u32(const void* p) {
    return (unsigned)__cvta_generic_to_shared(p);
}

static __device__ __forceinline__ void mbar_init(unsigned mbar, unsigned count) {
    asm volatile("mbarrier.init.shared.b64 [%0], %1;" :: "r"(mbar), "r"(count) : "memory");
}

static __device__ __forceinline__ void mbar_expect_tx(unsigned mbar, unsigned bytes) {
    asm volatile("mbarrier.arrive.expect_tx.shared.b64 _, [%0], %1;"
                 :: "r"(mbar), "r"(bytes) : "memory");
}

static __device__ __forceinline__ void mbar_wait(unsigned mbar, unsigned parity) {
    asm volatile(
        "{\n\t"
        ".reg .pred P1;\n\t"
        "LAB_WAIT_%=:\n\t"
        "mbarrier.try_wait.parity.acquire.cta.shared::cta.b64 P1, [%0], %1, 0x989680;\n\t"
        "@P1 bra LAB_DONE_%=;\n\t"
        "bra LAB_WAIT_%=;\n\t"
        "LAB_DONE_%=:\n\t"
        "}"
        :: "r"(mbar), "r"(parity) : "memory");
}

static __device__ __forceinline__ void bulk_g2s(unsigned dst_smem, const void* gsrc,
                                                unsigned bytes, unsigned mbar) {
    asm volatile(
        "cp.async.bulk.shared::cta.global.mbarrier::complete_tx::bytes [%0], [%1], %2, [%3];"
        :: "r"(dst_smem), "l"(gsrc), "r"(bytes), "r"(mbar) : "memory");
}

static __device__ __forceinline__ float lif_step(float v, float i, float& s_out) {
    float x  = i - v;                  // (-(v - 0) + i)
    float q0 = x * 0.1f;               // Markstein: correctly-rounded x/10
    float e  = fmaf(-10.0f, q0, x);
    float q  = fmaf(e, 0.1f, q0);
    v = v + q;
    s_out = (v >= 1.0f) ? 1.0f : 0.0f;
    return (v >= 1.0f) ? 0.0f : v;
}

// Warp 0 only. Lane 0 posts expect_tx; lanes 0..TC-1 each issue one 1 KB
// row copy. Warp program order puts expect_tx before the copies.
static __device__ __forceinline__ void issue_chunk_warp0(LifSmem* sm, int c,
                                                         const float* gsrc, int lane) {
    const int s = c % NSTAGE;
    const unsigned mb = smem_u32(&sm->mbar[s]);
    if (lane == 0) mbar_expect_tx(mb, STAGE_BYTES);
    if (lane < TC) {
        const float* src = gsrc + (long long)(c * TC + lane) * LIF_N;
        bulk_g2s(smem_u32(&sm->tile[s][lane][0]), src, ROW_BYTES, mb);
    }
}

static __global__ __launch_bounds__(NTHREAD)
void lif_scan_kernel(const float* __restrict__ in,
                     const float* __restrict__ v0,
                     float* __restrict__ out)
{
    extern __shared__ char smem_raw[];
    LifSmem* sm = reinterpret_cast<LifSmem*>(smem_raw);

    const int tid  = threadIdx.x;
    const int lane = tid & 31;
    const int b    = blockIdx.x >> 2;          // 32 batches
    const int n0   = (blockIdx.x & 3) * NPC;   // 4 neuron-blocks of 256
    const int n    = n0 + tid * 4;             // this thread's first neuron

    if (tid == 0) {
        #pragma unroll
        for (int i = 0; i < NSTAGE; ++i)
            mbar_init(smem_u32(&sm->mbar[i]), 1);
        asm volatile("fence.proxy.async.shared::cta;" ::: "memory");
    }
    __syncthreads();

    const float* gsrc = in + (long long)b * (LIF_T * LIF_N) + n0;

    // Prologue: fill all pipeline stages (warp 0, lane-parallel issue).
    if (tid < 32) {
        #pragma unroll
        for (int c = 0; c < NSTAGE; ++c)
            issue_chunk_warp0(sm, c, gsrc, lane);
    }

    // Per-thread state: 4 neurons.
    float4 v = *(const float4*)(v0 + (long long)b * LIF_N + n);

    float* sp = out + (long long)b * (LIF_T * LIF_N) + n;          // spikes
    float* vp = sp + (long long)LIF_B * LIF_T * LIF_N;             // voltages

    #pragma unroll 1
    for (int c = 0; c < NCHUNK; ++c) {
        const int s = c % NSTAGE;
        const unsigned parity = (c / NSTAGE) & 1;

        mbar_wait(smem_u32(&sm->mbar[s]), parity);

        #pragma unroll
        for (int r = 0; r < TC; ++r) {
            float4 cur = ((const float4*)&sm->tile[s][r][0])[tid];
            float4 spk;
            v.x = lif_step(v.x, cur.x, spk.x);
            v.y = lif_step(v.y, cur.y, spk.y);
            v.z = lif_step(v.z, cur.z, spk.z);
            v.w = lif_step(v.w, cur.w, spk.w);
            const long long off = (long long)(c * TC + r) * LIF_N;
            __stcs((float4*)(sp + off), spk);
            __stcs((float4*)(vp + off), v);
        }

        __syncthreads();   // both warps done reading stage s -> safe to refill

        if (tid < 32 && c + NSTAGE < NCHUNK)
            issue_chunk_warp0(sm, c + NSTAGE, gsrc, lane);
    }
}

extern "C" void kernel_launch(void* const* d_in, const int* in_sizes, int n_in,
                              void* d_out, int out_size)
{
    const float* in = (const float*)d_in[0];   // [B, T, N]
    const float* v0 = (const float*)d_in[1];   // [B, N]
    float* out = (float*)d_out;                // [2, B, T, N]

    (void)in_sizes; (void)n_in; (void)out_size;

    const int smem_bytes = (int)sizeof(LifSmem);   // ~120 KB -> 1 CTA/SM
    cudaFuncSetAttribute(lif_scan_kernel,
                         cudaFuncAttributeMaxDynamicSharedMemorySize, smem_bytes);

    lif_scan_kernel<<<NCTA, NTHREAD, smem_bytes>>>(in, v0, out);
}